// round 1
// baseline (speedup 1.0000x reference)
#include <cuda_runtime.h>

// out[m,k] = D*(w-1)*sum_j tensor[m,j], broadcast over k (D = OUTPUT_DIM = 2048)
// M = 16384, D = 2048. Pure HBM-bound: 128 MiB read + 128 MiB write.

#define M_ROWS 16384
#define D_COLS 2048
#define VEC_PER_ROW (D_COLS / 4)   // 512 float4
#define NTHREADS 256

__global__ __launch_bounds__(NTHREADS)
void perm_equiv_kernel(const float* __restrict__ t,
                       const float* __restrict__ w,
                       float* __restrict__ out) {
    const int m = blockIdx.x;
    const int tid = threadIdx.x;

    const float4* __restrict__ row = reinterpret_cast<const float4*>(t + (size_t)m * D_COLS);

    // Phase 1: per-thread partial sum over 2 float4 (512 vec / 256 threads)
    float4 a = row[tid];
    float4 b = row[tid + NTHREADS];
    float s = (a.x + a.y) + (a.z + a.w) + (b.x + b.y) + (b.z + b.w);

    // Warp reduction
    #pragma unroll
    for (int off = 16; off > 0; off >>= 1)
        s += __shfl_down_sync(0xFFFFFFFFu, s, off);

    // Block reduction across 8 warps
    __shared__ float warp_sums[NTHREADS / 32];
    __shared__ float bcast;
    const int lane = tid & 31;
    const int wid  = tid >> 5;
    if (lane == 0) warp_sums[wid] = s;
    __syncthreads();

    if (tid == 0) {
        float total = warp_sums[0];
        #pragma unroll
        for (int i = 1; i < NTHREADS / 32; i++) total += warp_sums[i];
        const float scale = (float)D_COLS * (w[0] - 1.0f);
        bcast = scale * total;
    }
    __syncthreads();

    // Phase 2: broadcast write of the row
    const float v = bcast;
    const float4 vv = make_float4(v, v, v, v);
    float4* __restrict__ orow = reinterpret_cast<float4*>(out + (size_t)m * D_COLS);
    orow[tid] = vv;
    orow[tid + NTHREADS] = vv;
}

extern "C" void kernel_launch(void* const* d_in, const int* in_sizes, int n_in,
                              void* d_out, int out_size) {
    const float* t = (const float*)d_in[0];
    const float* w = (const float*)d_in[1];
    float* out = (float*)d_out;
    perm_equiv_kernel<<<M_ROWS, NTHREADS>>>(t, w, out);
}